// round 1
// baseline (speedup 1.0000x reference)
#include <cuda_runtime.h>
#include <math.h>
#include <stdint.h>

// ---------------- problem constants ----------------
#define BATCH 2048
#define FDIM  512
#define MDIM  16
#define HH    32
#define WW    32
#define PD    64
#define KS    11
#define KK    (KS*KS)          // 121
#define HW    (HH*WW)          // 1024
#define SIGMA (11.0f/3.0f)

#define OUT0  (BATCH*576)      // offset of 'updated' in d_out

// ---------------- scratch (static device globals; no allocation) ----------------
__device__ float g_x  [BATCH*576];
__device__ float g_h1 [BATCH*256];
__device__ float g_h2 [BATCH*128];
__device__ float g_wv [BATCH*1936];
__device__ float g_wt1[9*16*128];          // ck1 transposed [tap][ic][oc]
__device__ float g_wt2[9*128*64];          // ck2 transposed
__device__ float g_y1 [(size_t)BATCH*128*HW];   // 1.07 GB
__device__ float g_y2 [(size_t)BATCH*64*HW];    // 0.54 GB
__device__ float g_pool[BATCH*576];

// ---------------- 1) build x = concat(features, pos_encoding(gaze)) ----------------
__global__ void build_x_kernel(const float* __restrict__ features,
                               const float* __restrict__ gaze,
                               float* __restrict__ x) {
    int idx = blockIdx.x * blockDim.x + threadIdx.x;
    if (idx >= BATCH * 576) return;
    int b = idx / 576, j = idx % 576;
    if (j < FDIM) { x[idx] = features[(size_t)b * FDIM + j]; return; }
    int jj = j - FDIM;
    int axis = jj >> 5;        // 0: x-axis, 1: y-axis
    int r = jj & 31;
    int di = r >> 1;
    float d = expf(-(float)(2 * di) * (logf(10000.0f) / 32.0f));
    float arg = gaze[b * 2 + axis] * d;
    x[idx] = (r & 1) ? cosf(arg) : sinf(arg);
}

// ---------------- generic fp32 GEMM: C[M,N] = act(A[M,K] @ W[K,N] + bias) --------
// BM=128, BN=64, BK=16, 256 threads, 8x4 register tile per thread.
template<bool RELU>
__global__ void gemm_kernel(const float* __restrict__ A, const float* __restrict__ Wt,
                            const float* __restrict__ bias, float* __restrict__ C,
                            int Kdim, int Ndim) {
    __shared__ float As[128][17];
    __shared__ float Bs[16][64];
    int t = threadIdx.x;
    int row0 = blockIdx.x * 128;
    int col0 = blockIdx.y * 64;
    int pr = (t >> 4) * 8;
    int pc = (t & 15) * 4;
    float acc[8][4] = {};
    for (int k0 = 0; k0 < Kdim; k0 += 16) {
        #pragma unroll
        for (int i = 0; i < 8; i++) {
            int idx = t + i * 256;
            int kk = idx & 15, rr = idx >> 4;
            As[rr][kk] = A[(size_t)(row0 + rr) * Kdim + k0 + kk];
        }
        #pragma unroll
        for (int i = 0; i < 4; i++) {
            int idx = t + i * 256;
            int nn = idx & 63, kk = idx >> 6;
            int gn = col0 + nn;
            Bs[kk][nn] = (gn < Ndim) ? Wt[(size_t)(k0 + kk) * Ndim + gn] : 0.0f;
        }
        __syncthreads();
        #pragma unroll
        for (int kk = 0; kk < 16; kk++) {
            float bvv[4];
            *(float4*)bvv = *(const float4*)&Bs[kk][pc];
            #pragma unroll
            for (int r = 0; r < 8; r++) {
                float a = As[pr + r][kk];
                acc[r][0] += a * bvv[0];
                acc[r][1] += a * bvv[1];
                acc[r][2] += a * bvv[2];
                acc[r][3] += a * bvv[3];
            }
        }
        __syncthreads();
    }
    #pragma unroll
    for (int c = 0; c < 4; c++) {
        int gc = col0 + pc + c;
        if (gc >= Ndim) continue;
        float bb = bias[gc];
        #pragma unroll
        for (int r = 0; r < 8; r++) {
            float v = acc[r][c] + bb;
            if (RELU) v = fmaxf(v, 0.0f);
            C[(size_t)(row0 + pr + r) * Ndim + gc] = v;
        }
    }
}

// ---------------- gate + weighted scatter + cell update (1 block / batch) --------
__global__ void gate_scatter_kernel(const float* __restrict__ cell,
                                    const float* __restrict__ gaze,
                                    const float* __restrict__ wv,
                                    const float* __restrict__ ws1,
                                    const float* __restrict__ bs1,
                                    const float* __restrict__ ws2,
                                    const float* __restrict__ bs2,
                                    float* __restrict__ updated_out) {
    extern __shared__ float sm[];
    float* num  = sm;                 // 1024*17
    float* den  = sm + 1024 * 17;     // 1024
    float* ws1s = den + 1024;         // 32*64
    float* red  = ws1s + 2048;        // 128
    int b = blockIdx.x, t = threadIdx.x;

    for (int i = t; i < 1024 * 17 + 1024; i += 128) sm[i] = 0.0f;
    for (int i = t; i < 2048; i += 128) ws1s[i] = ws1[i];

    float gx = fminf(fmaxf(gaze[b * 2 + 0] * (WW - 1), 0.0f), (float)(WW - 1));
    float gy = fminf(fmaxf(gaze[b * 2 + 1] * (HH - 1), 0.0f), (float)(HH - 1));
    int x0 = (int)floorf(gx), y0 = (int)floorf(gy);

    int k = t;
    float gauss = 0.0f; int xs = 0, ys = 0;
    if (k < KK) {
        int ox = k % KS - (KS / 2);
        int oy = k / KS - (KS / 2);
        xs = min(max(x0 + ox, 0), WW - 1);
        ys = min(max(y0 + oy, 0), HH - 1);
        float dx = (float)xs - gx, dy = (float)ys - gy;
        gauss = expf(-(dx * dx + dy * dy) / (2.0f * SIGMA * SIGMA));
    }
    red[t] = gauss;
    __syncthreads();
    for (int s = 64; s > 0; s >>= 1) {
        if (t < s) red[t] += red[t + s];
        __syncthreads();
    }
    float nsum = fmaxf(red[0], 1e-8f);

    if (k < KK) {
        float nw = gauss / nsum;
        int p = ys * WW + xs;
        float prev[MDIM], wval[MDIM];
        const float* cb = cell + (size_t)b * (MDIM * HW);
        #pragma unroll
        for (int m = 0; m < MDIM; m++) prev[m] = cb[m * HW + p];
        const float* wvb = wv + (size_t)b * (KK * MDIM) + k * MDIM;
        #pragma unroll
        for (int m = 0; m < MDIM; m++) wval[m] = wvb[m];

        float acc = bs2[0];
        for (int j = 0; j < 64; j++) {
            float s = bs1[j];
            #pragma unroll
            for (int i = 0; i < MDIM; i++) s += prev[i] * ws1s[i * 64 + j];
            #pragma unroll
            for (int i = 0; i < MDIM; i++) s += wval[i] * ws1s[(MDIM + i) * 64 + j];
            s = fmaxf(s, 0.0f);
            acc += s * ws2[j];
        }
        float gstr = 1.0f / (1.0f + expf(-acc));
        float w = nw * gstr;
        atomicAdd(&den[p], w);
        #pragma unroll
        for (int m = 0; m < MDIM; m++) {
            float nv = (1.0f - w) * prev[m] + w * wval[m];
            atomicAdd(&num[p * 17 + m], w * nv);
        }
    }
    __syncthreads();

    float* uo = updated_out + (size_t)b * (MDIM * HW);
    const float* cb = cell + (size_t)b * (MDIM * HW);
    for (int i = t; i < MDIM * HW; i += 128) {
        int p = i & (HW - 1);
        int m = i >> 10;
        float keep = 1.0f - fminf(den[p], 1.0f);
        uo[i] = keep * cb[i] + num[p * 17 + m];
    }
}

// ---------------- weight transpose: (OC,IC,3,3) -> [tap][ic][oc] -----------------
__global__ void transpose_w_kernel(const float* __restrict__ w, float* __restrict__ wt,
                                   int OC, int IC) {
    int idx = blockIdx.x * blockDim.x + threadIdx.x;
    int tot = OC * IC * 9;
    if (idx >= tot) return;
    int oc = idx / (IC * 9);
    int rem = idx - oc * (IC * 9);
    int ic = rem / 9;
    int tap = rem - ic * 9;
    wt[(size_t)tap * IC * OC + (size_t)ic * OC + oc] = w[idx];
}

// ---------------- 3x3 conv (SAME) + bias + relu as 9 shifted GEMMs ---------------
// grid: (px tiles = 8, oc tiles = OC/64, batch). 256 threads; 8px x 4oc per thread.
template<int IC, int OC>
__global__ void conv3x3_kernel(const float* __restrict__ in, const float* __restrict__ wt,
                               const float* __restrict__ bias, float* __restrict__ out) {
    __shared__ float As[128][17];
    __shared__ float Bs[16][64];
    int t = threadIdx.x;
    int pxt = blockIdx.x;              // 0..7 (4 rows each)
    int oc0 = blockIdx.y * 64;
    int img = blockIdx.z;
    int y0 = pxt * 4;
    const float* inb = in + (size_t)img * IC * HW;
    int pr = (t >> 4) * 8;
    int pc = (t & 15) * 4;
    float acc[8][4] = {};

    for (int tap = 0; tap < 9; tap++) {
        int dy = tap / 3 - 1, dx = tap % 3 - 1;
        for (int icc = 0; icc < IC / 16; icc++) {
            #pragma unroll
            for (int i = 0; i < 8; i++) {
                int idx = t + i * 256;
                int p = idx & 127, ic = idx >> 7;
                int yy = y0 + (p >> 5) + dy;
                int xx = (p & 31) + dx;
                float v = 0.0f;
                if (yy >= 0 && yy < HH && xx >= 0 && xx < WW)
                    v = inb[(size_t)(icc * 16 + ic) * HW + yy * WW + xx];
                As[p][ic] = v;
            }
            const float* wb = wt + ((size_t)tap * IC + icc * 16) * OC + oc0;
            #pragma unroll
            for (int i = 0; i < 4; i++) {
                int idx = t + i * 256;
                int nn = idx & 63, kk = idx >> 6;
                Bs[kk][nn] = wb[(size_t)kk * OC + nn];
            }
            __syncthreads();
            #pragma unroll
            for (int kk = 0; kk < 16; kk++) {
                float bvv[4];
                *(float4*)bvv = *(const float4*)&Bs[kk][pc];
                #pragma unroll
                for (int r = 0; r < 8; r++) {
                    float a = As[pr + r][kk];
                    acc[r][0] += a * bvv[0];
                    acc[r][1] += a * bvv[1];
                    acc[r][2] += a * bvv[2];
                    acc[r][3] += a * bvv[3];
                }
            }
            __syncthreads();
        }
    }
    float* ob = out + (size_t)img * OC * HW + (size_t)pxt * 128;
    #pragma unroll
    for (int c = 0; c < 4; c++) {
        float bb = bias[oc0 + pc + c];
        #pragma unroll
        for (int r = 0; r < 8; r++) {
            float v = fmaxf(acc[r][c] + bb, 0.0f);
            ob[(size_t)(oc0 + pc + c) * HW + pr + r] = v;
        }
    }
}

// ---------------- adaptive avg pool 3x3 (one block per (b,c)) --------------------
__global__ void pool_kernel(const float* __restrict__ y2, float* __restrict__ pooled) {
    __shared__ float img[1024];
    int bc = blockIdx.x;
    int c = bc & 63, b = bc >> 6;
    const float* src = y2 + ((size_t)b * 64 + c) * HW;
    for (int i = threadIdx.x; i < 1024; i += blockDim.x) img[i] = src[i];
    __syncthreads();
    if (threadIdx.x < 9) {
        int i = threadIdx.x / 3, j = threadIdx.x % 3;
        int h0 = (i == 0) ? 0 : (i == 1 ? 10 : 21);
        int h1 = (i == 0) ? 11 : (i == 1 ? 22 : 32);
        int w0 = (j == 0) ? 0 : (j == 1 ? 10 : 21);
        int w1 = (j == 0) ? 11 : (j == 1 ? 22 : 32);
        float s = 0.0f;
        for (int y = h0; y < h1; y++)
            for (int x = w0; x < w1; x++) s += img[y * 32 + x];
        pooled[(size_t)b * 576 + c * 9 + threadIdx.x] = s / (float)((h1 - h0) * (w1 - w0));
    }
}

// ---------------- launch ----------------
extern "C" void kernel_launch(void* const* d_in, const int* in_sizes, int n_in,
                              void* d_out, int out_size) {
    const float* features = (const float*)d_in[0];
    const float* cell     = (const float*)d_in[1];
    const float* gaze     = (const float*)d_in[2];
    const float* w1  = (const float*)d_in[3];
    const float* b1  = (const float*)d_in[4];
    const float* w2  = (const float*)d_in[5];
    const float* b2  = (const float*)d_in[6];
    const float* wvw = (const float*)d_in[7];
    const float* bv  = (const float*)d_in[8];
    const float* ws1 = (const float*)d_in[9];
    const float* bs1 = (const float*)d_in[10];
    const float* ws2 = (const float*)d_in[11];
    const float* bs2 = (const float*)d_in[12];
    const float* ck1 = (const float*)d_in[13];
    const float* cb1 = (const float*)d_in[14];
    const float* ck2 = (const float*)d_in[15];
    const float* cb2 = (const float*)d_in[16];
    const float* wo  = (const float*)d_in[17];
    const float* bo  = (const float*)d_in[18];

    float* out = (float*)d_out;
    float* updated = out + OUT0;

    float *px, *ph1, *ph2, *pwv, *pwt1, *pwt2, *py1, *py2, *ppool;
    cudaGetSymbolAddress((void**)&px,   g_x);
    cudaGetSymbolAddress((void**)&ph1,  g_h1);
    cudaGetSymbolAddress((void**)&ph2,  g_h2);
    cudaGetSymbolAddress((void**)&pwv,  g_wv);
    cudaGetSymbolAddress((void**)&pwt1, g_wt1);
    cudaGetSymbolAddress((void**)&pwt2, g_wt2);
    cudaGetSymbolAddress((void**)&py1,  g_y1);
    cudaGetSymbolAddress((void**)&py2,  g_y2);
    cudaGetSymbolAddress((void**)&ppool,g_pool);

    // 1) x = [features, pe]
    build_x_kernel<<<(BATCH * 576 + 255) / 256, 256>>>(features, gaze, px);

    // 2) MLP chain
    {
        dim3 g(BATCH / 128, 256 / 64);
        gemm_kernel<true><<<g, 256>>>(px, w1, b1, ph1, 576, 256);
    }
    {
        dim3 g(BATCH / 128, 128 / 64);
        gemm_kernel<true><<<g, 256>>>(ph1, w2, b2, ph2, 256, 128);
    }
    {
        dim3 g(BATCH / 128, (1936 + 63) / 64);
        gemm_kernel<false><<<g, 256>>>(ph2, wvw, bv, pwv, 128, 1936);
    }

    // 3) gate + scatter -> updated (written directly into d_out region)
    {
        size_t smem = (size_t)(1024 * 17 + 1024 + 2048 + 128) * sizeof(float);
        cudaFuncSetAttribute(gate_scatter_kernel,
                             cudaFuncAttributeMaxDynamicSharedMemorySize, (int)smem);
        gate_scatter_kernel<<<BATCH, 128, smem>>>(cell, gaze, pwv, ws1, bs1, ws2, bs2, updated);
    }

    // 4) conv weight transposes
    transpose_w_kernel<<<(128 * 16 * 9 + 255) / 256, 256>>>(ck1, pwt1, 128, 16);
    transpose_w_kernel<<<(64 * 128 * 9 + 255) / 256, 256>>>(ck2, pwt2, 64, 128);

    // 5) conv1: (B,16,32,32) -> (B,128,32,32) relu
    {
        dim3 g(8, 2, BATCH);
        conv3x3_kernel<16, 128><<<g, 256>>>(updated, pwt1, cb1, py1);
    }
    // 6) conv2: (B,128,32,32) -> (B,64,32,32) relu
    {
        dim3 g(8, 1, BATCH);
        conv3x3_kernel<128, 64><<<g, 256>>>(py1, pwt2, cb2, py2);
    }

    // 7) adaptive pool -> (B,576)
    pool_kernel<<<BATCH * 64, 128>>>(py2, ppool);

    // 8) final linear -> out (B,576)
    {
        dim3 g(BATCH / 128, (576 + 63) / 64);
        gemm_kernel<false><<<g, 256>>>(ppool, wo, bo, out, 576, 576);
    }
}

// round 3
// speedup vs baseline: 4.5624x; 4.5624x over previous
#include <cuda_runtime.h>
#include <cuda_fp16.h>
#include <math.h>
#include <stdint.h>

// ---------------- problem constants ----------------
#define BATCH 2048
#define FDIM  512
#define MDIM  16
#define HH    32
#define WW    32
#define PD    64
#define KS    11
#define KK    (KS*KS)          // 121
#define HW    (HH*WW)          // 1024
#define SIGMA (11.0f/3.0f)

#define OUT0  (BATCH*576)      // offset of 'updated' in d_out

// ---------------- scratch (static device globals; no allocation) ----------------
__device__ float g_x  [BATCH*576];
__device__ float g_h1 [BATCH*256];
__device__ float g_h2 [BATCH*128];
__device__ float g_wv [BATCH*1936];
__device__ __half g_wh1[9*2*64*16];              // conv1 weights fp16 [tap][octile][oc64][ic16]
__device__ __half g_wh2[9*1*64*128];             // conv2 weights fp16 [tap][0][oc64][ic128]
__device__ __half g_y1h[(size_t)BATCH*HW*128];   // conv1 out, NHWC fp16, 537 MB
__device__ __half g_y2h[(size_t)BATCH*HW*64];    // conv2 out, NHWC fp16, 268 MB
__device__ float g_pool[BATCH*576];

// ---------------- mma / ldmatrix helpers ----------------
__device__ __forceinline__ void ldsm4(uint32_t* r, const __half* p) {
    uint32_t addr = (uint32_t)__cvta_generic_to_shared(p);
    asm volatile("ldmatrix.sync.aligned.m8n8.x4.shared.b16 {%0,%1,%2,%3}, [%4];\n"
        : "=r"(r[0]), "=r"(r[1]), "=r"(r[2]), "=r"(r[3]) : "r"(addr));
}
__device__ __forceinline__ void mma16816(float* c, const uint32_t* a, uint32_t b0, uint32_t b1) {
    asm volatile("mma.sync.aligned.m16n8k16.row.col.f32.f16.f16.f32 "
        "{%0,%1,%2,%3}, {%4,%5,%6,%7}, {%8,%9}, {%0,%1,%2,%3};\n"
        : "+f"(c[0]), "+f"(c[1]), "+f"(c[2]), "+f"(c[3])
        : "r"(a[0]), "r"(a[1]), "r"(a[2]), "r"(a[3]), "r"(b0), "r"(b1));
}

// ---------------- 1) build x = concat(features, pos_encoding(gaze)) ----------------
__global__ void build_x_kernel(const float* __restrict__ features,
                               const float* __restrict__ gaze,
                               float* __restrict__ x) {
    int idx = blockIdx.x * blockDim.x + threadIdx.x;
    if (idx >= BATCH * 576) return;
    int b = idx / 576, j = idx % 576;
    if (j < FDIM) { x[idx] = features[(size_t)b * FDIM + j]; return; }
    int jj = j - FDIM;
    int axis = jj >> 5;
    int r = jj & 31;
    int di = r >> 1;
    float d = expf(-(float)(2 * di) * (logf(10000.0f) / 32.0f));
    float arg = gaze[b * 2 + axis] * d;
    x[idx] = (r & 1) ? cosf(arg) : sinf(arg);
}

// ---------------- generic fp32 GEMM (small MLPs) --------------------------------
template<bool RELU>
__global__ void gemm_kernel(const float* __restrict__ A, const float* __restrict__ Wt,
                            const float* __restrict__ bias, float* __restrict__ C,
                            int Kdim, int Ndim) {
    __shared__ float As[128][17];
    __shared__ float Bs[16][64];
    int t = threadIdx.x;
    int row0 = blockIdx.x * 128;
    int col0 = blockIdx.y * 64;
    int pr = (t >> 4) * 8;
    int pc = (t & 15) * 4;
    float acc[8][4] = {};
    for (int k0 = 0; k0 < Kdim; k0 += 16) {
        #pragma unroll
        for (int i = 0; i < 8; i++) {
            int idx = t + i * 256;
            int kk = idx & 15, rr = idx >> 4;
            As[rr][kk] = A[(size_t)(row0 + rr) * Kdim + k0 + kk];
        }
        #pragma unroll
        for (int i = 0; i < 4; i++) {
            int idx = t + i * 256;
            int nn = idx & 63, kk = idx >> 6;
            int gn = col0 + nn;
            Bs[kk][nn] = (gn < Ndim) ? Wt[(size_t)(k0 + kk) * Ndim + gn] : 0.0f;
        }
        __syncthreads();
        #pragma unroll
        for (int kk = 0; kk < 16; kk++) {
            float bvv[4];
            *(float4*)bvv = *(const float4*)&Bs[kk][pc];
            #pragma unroll
            for (int r = 0; r < 8; r++) {
                float a = As[pr + r][kk];
                acc[r][0] += a * bvv[0];
                acc[r][1] += a * bvv[1];
                acc[r][2] += a * bvv[2];
                acc[r][3] += a * bvv[3];
            }
        }
        __syncthreads();
    }
    #pragma unroll
    for (int c = 0; c < 4; c++) {
        int gc = col0 + pc + c;
        if (gc >= Ndim) continue;
        float bb = bias[gc];
        #pragma unroll
        for (int r = 0; r < 8; r++) {
            float v = acc[r][c] + bb;
            if (RELU) v = fmaxf(v, 0.0f);
            C[(size_t)(row0 + pr + r) * Ndim + gc] = v;
        }
    }
}

// ---------------- gate + weighted scatter + cell update (1 block / batch) --------
__global__ void gate_scatter_kernel(const float* __restrict__ cell,
                                    const float* __restrict__ gaze,
                                    const float* __restrict__ wv,
                                    const float* __restrict__ ws1,
                                    const float* __restrict__ bs1,
                                    const float* __restrict__ ws2,
                                    const float* __restrict__ bs2,
                                    float* __restrict__ updated_out) {
    extern __shared__ float sm[];
    float* num  = sm;                 // 1024*17
    float* den  = sm + 1024 * 17;     // 1024
    float* ws1s = den + 1024;         // 32*64
    float* red  = ws1s + 2048;        // 128
    int b = blockIdx.x, t = threadIdx.x;

    for (int i = t; i < 1024 * 17 + 1024; i += 128) sm[i] = 0.0f;
    for (int i = t; i < 2048; i += 128) ws1s[i] = ws1[i];

    float gx = fminf(fmaxf(gaze[b * 2 + 0] * (WW - 1), 0.0f), (float)(WW - 1));
    float gy = fminf(fmaxf(gaze[b * 2 + 1] * (HH - 1), 0.0f), (float)(HH - 1));
    int x0 = (int)floorf(gx), y0 = (int)floorf(gy);

    int k = t;
    float gauss = 0.0f; int xs = 0, ys = 0;
    if (k < KK) {
        int ox = k % KS - (KS / 2);
        int oy = k / KS - (KS / 2);
        xs = min(max(x0 + ox, 0), WW - 1);
        ys = min(max(y0 + oy, 0), HH - 1);
        float dx = (float)xs - gx, dy = (float)ys - gy;
        gauss = expf(-(dx * dx + dy * dy) / (2.0f * SIGMA * SIGMA));
    }
    red[t] = gauss;
    __syncthreads();
    for (int s = 64; s > 0; s >>= 1) {
        if (t < s) red[t] += red[t + s];
        __syncthreads();
    }
    float nsum = fmaxf(red[0], 1e-8f);

    if (k < KK) {
        float nw = gauss / nsum;
        int p = ys * WW + xs;
        float prev[MDIM], wval[MDIM];
        const float* cb = cell + (size_t)b * (MDIM * HW);
        #pragma unroll
        for (int m = 0; m < MDIM; m++) prev[m] = cb[m * HW + p];
        const float* wvb = wv + (size_t)b * (KK * MDIM) + k * MDIM;
        #pragma unroll
        for (int m = 0; m < MDIM; m++) wval[m] = wvb[m];

        float acc = bs2[0];
        for (int j = 0; j < 64; j++) {
            float s = bs1[j];
            #pragma unroll
            for (int i = 0; i < MDIM; i++) s += prev[i] * ws1s[i * 64 + j];
            #pragma unroll
            for (int i = 0; i < MDIM; i++) s += wval[i] * ws1s[(MDIM + i) * 64 + j];
            s = fmaxf(s, 0.0f);
            acc += s * ws2[j];
        }
        float gstr = 1.0f / (1.0f + expf(-acc));
        float w = nw * gstr;
        atomicAdd(&den[p], w);
        #pragma unroll
        for (int m = 0; m < MDIM; m++) {
            float nv = (1.0f - w) * prev[m] + w * wval[m];
            atomicAdd(&num[p * 17 + m], w * nv);
        }
    }
    __syncthreads();

    float* uo = updated_out + (size_t)b * (MDIM * HW);
    const float* cb = cell + (size_t)b * (MDIM * HW);
    for (int i = t; i < MDIM * HW; i += 128) {
        int p = i & (HW - 1);
        int m = i >> 10;
        float keep = 1.0f - fminf(den[p], 1.0f);
        uo[i] = keep * cb[i] + num[p * 17 + m];
    }
}

// ---- conv weight prep: (OC,IC,3,3) fp32 -> [tap][oc/64][oc%64][ic] fp16 ----------
__global__ void prep_w_kernel(const float* __restrict__ w, __half* __restrict__ wh,
                              int OC, int IC) {
    int idx = blockIdx.x * blockDim.x + threadIdx.x;
    int tot = OC * IC * 9;
    if (idx >= tot) return;
    int oc = idx / (IC * 9);
    int rem = idx - oc * (IC * 9);
    int ic = rem / 9;
    int tap = rem - ic * 9;
    size_t dst = ((size_t)(tap * (OC / 64) + (oc >> 6)) * 64 + (oc & 63)) * IC + ic;
    wh[dst] = __float2half(w[idx]);
}

// ---------------- tensor-core 3x3 conv (SAME) + bias + relu ----------------------
// Implicit GEMM, tap-decomposed. Block: 256 thr (8 warps, 4Mx2N), tile 128px x 64oc.
// IN_F32: input fp32 NCHW (conv1).  Else: input fp16 NHWC.
// Output: fp16 NHWC [img][hw][OC].
template<int IC, int OC, bool IN_F32>
__global__ void conv_mma_kernel(const void* __restrict__ in_,
                                const __half* __restrict__ wh,
                                const float* __restrict__ bias,
                                __half* __restrict__ out) {
    constexpr int SA = IC + 8;          // smem row stride (halves), conflict-free for ldmatrix
    constexpr int SO = 80;              // output staging stride
    extern __shared__ char smraw[];
    __half* As = (__half*)smraw;                     // 128 x SA
    __half* Bs = As + 128 * SA;                      // 64 x SA
    __half* Os = (128 * SA >= 128 * SO) ? As : (Bs + 64 * SA);

    int t = threadIdx.x;
    int lane = t & 31, warp = t >> 5;
    int wm = warp & 3, wn = warp >> 2;               // 4 x 2 warp grid
    int pxt = blockIdx.x;                            // 8 px tiles (4 rows each)
    int oc0g = blockIdx.y * 64;
    int img = blockIdx.z;
    int y0 = pxt * 4;

    const float* inF = (const float*)in_;
    const __half* inH = (const __half*)in_;
    const float* inFb = inF + (size_t)img * IC * HW;   // NCHW
    const __half* inHb = inH + (size_t)img * HW * IC;  // NHWC

    float acc[2][4][4] = {};

    for (int tap = 0; tap < 9; tap++) {
        int dy = tap / 3 - 1, dx = tap % 3 - 1;
        // ---- load A tile: 128 px x IC halves ----
        if (IN_F32) {
            #pragma unroll
            for (int i = 0; i < (128 * IC) / 256; i++) {
                int idx = t + i * 256;
                int ic = idx >> 7, p = idx & 127;
                int yy = y0 + (p >> 5) + dy, xx = (p & 31) + dx;
                float v = 0.0f;
                if (yy >= 0 && yy < HH && xx >= 0 && xx < WW)
                    v = inFb[(size_t)ic * HW + yy * WW + xx];
                As[p * SA + ic] = __float2half(v);
            }
        } else {
            constexpr int RV = IC / 8;               // uint4 per px row
            #pragma unroll
            for (int i = 0; i < (128 * RV) / 256; i++) {
                int idx = t + i * 256;
                int p = idx / RV, ch = idx % RV;
                int yy = y0 + (p >> 5) + dy, xx = (p & 31) + dx;
                uint4 v = make_uint4(0, 0, 0, 0);
                if (yy >= 0 && yy < HH && xx >= 0 && xx < WW)
                    v = *(const uint4*)(inHb + (size_t)(yy * WW + xx) * IC + ch * 8);
                *(uint4*)(As + p * SA + ch * 8) = v;
            }
        }
        // ---- load B tile: 64 oc x IC halves ----
        {
            constexpr int RV = IC / 8;
            const __half* wb = wh + ((size_t)(tap * (OC / 64) + blockIdx.y) * 64) * IC;
            for (int i = 0; i < (64 * RV + 255) / 256; i++) {
                int idx = t + i * 256;
                if (idx < 64 * RV) {
                    int oc = idx / RV, ch = idx % RV;
                    *(uint4*)(Bs + oc * SA + ch * 8) = *(const uint4*)(wb + oc * IC + ch * 8);
                }
            }
        }
        __syncthreads();
        // ---- mma over K = IC ----
        #pragma unroll
        for (int ks = 0; ks < IC / 16; ks++) {
            uint32_t a[2][4], b[2][4];
            #pragma unroll
            for (int mf = 0; mf < 2; mf++) {
                int row = wm * 32 + mf * 16 + (lane & 15);
                int col = ks * 16 + (lane >> 4) * 8;
                ldsm4(a[mf], As + row * SA + col);
            }
            #pragma unroll
            for (int nf2 = 0; nf2 < 2; nf2++) {
                int n = wn * 32 + nf2 * 16 + (lane & 7) + (lane >> 4) * 8;
                int col = ks * 16 + ((lane >> 3) & 1) * 8;
                ldsm4(b[nf2], Bs + n * SA + col);
            }
            #pragma unroll
            for (int mf = 0; mf < 2; mf++)
                #pragma unroll
                for (int nf = 0; nf < 4; nf++)
                    mma16816(acc[mf][nf], a[mf], b[nf >> 1][(nf & 1) * 2], b[nf >> 1][(nf & 1) * 2 + 1]);
        }
        __syncthreads();
    }

    // ---- stage output [px][oc] fp16 (bias + relu) ----
    #pragma unroll
    for (int mf = 0; mf < 2; mf++) {
        #pragma unroll
        for (int nf = 0; nf < 4; nf++) {
            int px = wm * 32 + mf * 16 + (lane >> 2);
            int oc = wn * 32 + nf * 8 + 2 * (lane & 3);
            float bb0 = bias[oc0g + oc], bb1 = bias[oc0g + oc + 1];
            float v0 = fmaxf(acc[mf][nf][0] + bb0, 0.0f);
            float v1 = fmaxf(acc[mf][nf][1] + bb1, 0.0f);
            *(__half2*)(Os + px * SO + oc) = __floats2half2_rn(v0, v1);
            v0 = fmaxf(acc[mf][nf][2] + bb0, 0.0f);
            v1 = fmaxf(acc[mf][nf][3] + bb1, 0.0f);
            *(__half2*)(Os + (px + 8) * SO + oc) = __floats2half2_rn(v0, v1);
        }
    }
    __syncthreads();
    // ---- coalesced NHWC store ----
    __half* ob = out + (size_t)img * HW * OC;
    int hw0 = pxt * 128;
    #pragma unroll
    for (int i = 0; i < 4; i++) {
        int idx = t + i * 256;                 // 1024 uint4 = 128px x 64oc halves
        int px = idx >> 3, ch = idx & 7;
        *(uint4*)(ob + (size_t)(hw0 + px) * OC + oc0g + ch * 8) = *(uint4*)(Os + px * SO + ch * 8);
    }
}

// ---------------- adaptive avg pool 3x3 from NHWC fp16 --------------------------
__global__ void pool_nhwc_kernel(const __half* __restrict__ y2, float* __restrict__ pooled) {
    int b = blockIdx.x, t = threadIdx.x;     // 576 threads: t = cell*64 + c
    int c = t & 63, cell = t >> 6;
    int i = cell / 3, j = cell % 3;
    int h0 = (i == 0) ? 0 : (i == 1 ? 10 : 21);
    int h1 = (i == 0) ? 11 : (i == 1 ? 22 : 32);
    int w0 = (j == 0) ? 0 : (j == 1 ? 10 : 21);
    int w1 = (j == 0) ? 11 : (j == 1 ? 22 : 32);
    const __half* src = y2 + (size_t)b * HW * 64 + c;
    float s = 0.0f;
    for (int y = h0; y < h1; y++)
        for (int x = w0; x < w1; x++)
            s += __half2float(src[(size_t)(y * WW + x) * 64]);
    pooled[(size_t)b * 576 + c * 9 + cell] = s / (float)((h1 - h0) * (w1 - w0));
}

// ---------------- launch ----------------
extern "C" void kernel_launch(void* const* d_in, const int* in_sizes, int n_in,
                              void* d_out, int out_size) {
    const float* features = (const float*)d_in[0];
    const float* cell     = (const float*)d_in[1];
    const float* gaze     = (const float*)d_in[2];
    const float* w1  = (const float*)d_in[3];
    const float* b1  = (const float*)d_in[4];
    const float* w2  = (const float*)d_in[5];
    const float* b2  = (const float*)d_in[6];
    const float* wvw = (const float*)d_in[7];
    const float* bv  = (const float*)d_in[8];
    const float* ws1 = (const float*)d_in[9];
    const float* bs1 = (const float*)d_in[10];
    const float* ws2 = (const float*)d_in[11];
    const float* bs2 = (const float*)d_in[12];
    const float* ck1 = (const float*)d_in[13];
    const float* cb1 = (const float*)d_in[14];
    const float* ck2 = (const float*)d_in[15];
    const float* cb2 = (const float*)d_in[16];
    const float* wo  = (const float*)d_in[17];
    const float* bo  = (const float*)d_in[18];

    float* out = (float*)d_out;
    float* updated = out + OUT0;

    float *px, *ph1, *ph2, *pwv, *ppool;
    __half *pwh1, *pwh2, *py1h, *py2h;
    cudaGetSymbolAddress((void**)&px,   g_x);
    cudaGetSymbolAddress((void**)&ph1,  g_h1);
    cudaGetSymbolAddress((void**)&ph2,  g_h2);
    cudaGetSymbolAddress((void**)&pwv,  g_wv);
    cudaGetSymbolAddress((void**)&pwh1, g_wh1);
    cudaGetSymbolAddress((void**)&pwh2, g_wh2);
    cudaGetSymbolAddress((void**)&py1h, g_y1h);
    cudaGetSymbolAddress((void**)&py2h, g_y2h);
    cudaGetSymbolAddress((void**)&ppool,g_pool);

    // 1) x = [features, pe]
    build_x_kernel<<<(BATCH * 576 + 255) / 256, 256>>>(features, gaze, px);

    // 2) MLP chain
    {
        dim3 g(BATCH / 128, 256 / 64);
        gemm_kernel<true><<<g, 256>>>(px, w1, b1, ph1, 576, 256);
    }
    {
        dim3 g(BATCH / 128, 128 / 64);
        gemm_kernel<true><<<g, 256>>>(ph1, w2, b2, ph2, 256, 128);
    }
    {
        dim3 g(BATCH / 128, (1936 + 63) / 64);
        gemm_kernel<false><<<g, 256>>>(ph2, wvw, bv, pwv, 128, 1936);
    }

    // 3) gate + scatter -> updated (into d_out region)
    {
        size_t smem = (size_t)(1024 * 17 + 1024 + 2048 + 128) * sizeof(float);
        cudaFuncSetAttribute(gate_scatter_kernel,
                             cudaFuncAttributeMaxDynamicSharedMemorySize, (int)smem);
        gate_scatter_kernel<<<BATCH, 128, smem>>>(cell, gaze, pwv, ws1, bs1, ws2, bs2, updated);
    }

    // 4) conv weight prep (fp32 -> fp16, transposed)
    prep_w_kernel<<<(128 * 16 * 9 + 255) / 256, 256>>>(ck1, pwh1, 128, 16);
    prep_w_kernel<<<(64 * 128 * 9 + 255) / 256, 256>>>(ck2, pwh2, 64, 128);

    // 5) conv1: (B,16,32,32) f32 NCHW -> (B,1024,128) f16 NHWC
    {
        constexpr int SMEM1 = (192 * 24) * 2 + 128 * 80 * 2;   // 29696
        dim3 g(8, 2, BATCH);
        conv_mma_kernel<16, 128, true><<<g, 256, SMEM1>>>(updated, pwh1, cb1, py1h);
    }
    // 6) conv2: (B,1024,128) f16 NHWC -> (B,1024,64) f16 NHWC
    {
        constexpr int SMEM2 = (192 * 136) * 2;                 // 52224 (Os aliases As)
        cudaFuncSetAttribute(conv_mma_kernel<128, 64, false>,
                             cudaFuncAttributeMaxDynamicSharedMemorySize, SMEM2);
        dim3 g(8, 1, BATCH);
        conv_mma_kernel<128, 64, false><<<g, 256, SMEM2>>>(py1h, pwh2, cb2, py2h);
    }

    // 7) adaptive pool -> (B,576) fp32
    pool_nhwc_kernel<<<BATCH, 576>>>(py2h, ppool);

    // 8) final linear -> out (B,576)
    {
        dim3 g(BATCH / 128, (576 + 63) / 64);
        gemm_kernel<false><<<g, 256>>>(ppool, wo, bo, out, 576, 576);
    }
}

// round 5
// speedup vs baseline: 6.1866x; 1.3560x over previous
#include <cuda_runtime.h>
#include <cuda_fp16.h>
#include <math.h>
#include <stdint.h>

// ---------------- problem constants ----------------
#define BATCH 2048
#define FDIM  512
#define MDIM  16
#define HH    32
#define WW    32
#define PD    64
#define KS    11
#define KK    (KS*KS)          // 121
#define HW    (HH*WW)          // 1024
#define SIGMA (11.0f/3.0f)
#define OUT0  (BATCH*576)      // offset of 'updated' in d_out

// ---------------- scratch (static device globals; no allocation) ----------------
__device__ float  g_x  [BATCH*576];
__device__ float  g_h1 [BATCH*256];
__device__ float  g_h2 [BATCH*128];
__device__ float  g_wv [BATCH*1936];
__device__ __half g_uph[(size_t)BATCH*HW*16];    // updated, fp16 NHWC (conv1 input)
__device__ __half g_wh1[128*144];                // conv1 W fp16 [oc][tap*16+ic]
__device__ __half g_wh2[9*64*128];               // conv2 W fp16 [tap][oc][ic]
__device__ __half g_y1h[(size_t)BATCH*HW*128];   // conv1 out, NHWC fp16
__device__ __half g_y2h[(size_t)BATCH*HW*64];    // conv2 out, NHWC fp16
__device__ float  g_pool[BATCH*576];

// ---------------- mma / ldmatrix / cp.async helpers ----------------
__device__ __forceinline__ void ldsm4(uint32_t* r, const __half* p) {
    uint32_t addr = (uint32_t)__cvta_generic_to_shared(p);
    asm volatile("ldmatrix.sync.aligned.m8n8.x4.shared.b16 {%0,%1,%2,%3}, [%4];\n"
        : "=r"(r[0]), "=r"(r[1]), "=r"(r[2]), "=r"(r[3]) : "r"(addr));
}
__device__ __forceinline__ void mma16816(float* c, const uint32_t* a, uint32_t b0, uint32_t b1) {
    asm volatile("mma.sync.aligned.m16n8k16.row.col.f32.f16.f16.f32 "
        "{%0,%1,%2,%3}, {%4,%5,%6,%7}, {%8,%9}, {%0,%1,%2,%3};\n"
        : "+f"(c[0]), "+f"(c[1]), "+f"(c[2]), "+f"(c[3])
        : "r"(a[0]), "r"(a[1]), "r"(a[2]), "r"(a[3]), "r"(b0), "r"(b1));
}
__device__ __forceinline__ void cpa16(const __half* dst, const void* src) {
    uint32_t d = (uint32_t)__cvta_generic_to_shared(dst);
    asm volatile("cp.async.cg.shared.global [%0], [%1], 16;" :: "r"(d), "l"(src));
}
#define CP_COMMIT() asm volatile("cp.async.commit_group;" ::: "memory")
#define CP_WAIT0()  asm volatile("cp.async.wait_group 0;" ::: "memory")

// ---------------- 1) build x = concat(features, pos_encoding(gaze)) ----------------
__global__ void build_x_kernel(const float* __restrict__ features,
                               const float* __restrict__ gaze,
                               float* __restrict__ x) {
    int idx = blockIdx.x * blockDim.x + threadIdx.x;
    if (idx >= BATCH * 576) return;
    int b = idx / 576, j = idx % 576;
    if (j < FDIM) { x[idx] = features[(size_t)b * FDIM + j]; return; }
    int jj = j - FDIM;
    int axis = jj >> 5;
    int r = jj & 31;
    int di = r >> 1;
    float d = expf(-(float)(2 * di) * (logf(10000.0f) / 32.0f));
    float arg = gaze[b * 2 + axis] * d;
    x[idx] = (r & 1) ? cosf(arg) : sinf(arg);
}

// ---------------- generic fp32 GEMM (small MLPs) --------------------------------
template<bool RELU>
__global__ void gemm_kernel(const float* __restrict__ A, const float* __restrict__ Wt,
                            const float* __restrict__ bias, float* __restrict__ C,
                            int Kdim, int Ndim) {
    __shared__ float As[128][17];
    __shared__ float Bs[16][64];
    int t = threadIdx.x;
    int row0 = blockIdx.x * 128;
    int col0 = blockIdx.y * 64;
    int pr = (t >> 4) * 8;
    int pc = (t & 15) * 4;
    float acc[8][4] = {};
    for (int k0 = 0; k0 < Kdim; k0 += 16) {
        #pragma unroll
        for (int i = 0; i < 8; i++) {
            int idx = t + i * 256;
            int kk = idx & 15, rr = idx >> 4;
            As[rr][kk] = A[(size_t)(row0 + rr) * Kdim + k0 + kk];
        }
        #pragma unroll
        for (int i = 0; i < 4; i++) {
            int idx = t + i * 256;
            int nn = idx & 63, kk = idx >> 6;
            int gn = col0 + nn;
            Bs[kk][nn] = (gn < Ndim) ? Wt[(size_t)(k0 + kk) * Ndim + gn] : 0.0f;
        }
        __syncthreads();
        #pragma unroll
        for (int kk = 0; kk < 16; kk++) {
            float bvv[4];
            *(float4*)bvv = *(const float4*)&Bs[kk][pc];
            #pragma unroll
            for (int r = 0; r < 8; r++) {
                float a = As[pr + r][kk];
                acc[r][0] += a * bvv[0];
                acc[r][1] += a * bvv[1];
                acc[r][2] += a * bvv[2];
                acc[r][3] += a * bvv[3];
            }
        }
        __syncthreads();
    }
    #pragma unroll
    for (int c = 0; c < 4; c++) {
        int gc = col0 + pc + c;
        if (gc >= Ndim) continue;
        float bb = bias[gc];
        #pragma unroll
        for (int r = 0; r < 8; r++) {
            float v = acc[r][c] + bb;
            if (RELU) v = fmaxf(v, 0.0f);
            C[(size_t)(row0 + pr + r) * Ndim + gc] = v;
        }
    }
}

// ---------------- gate + weighted scatter + cell update (1 block / batch) --------
__global__ void gate_scatter_kernel(const float* __restrict__ cell,
                                    const float* __restrict__ gaze,
                                    const float* __restrict__ wv,
                                    const float* __restrict__ ws1,
                                    const float* __restrict__ bs1,
                                    const float* __restrict__ ws2,
                                    const float* __restrict__ bs2,
                                    float* __restrict__ updated_out,
                                    __half* __restrict__ updated_h) {
    extern __shared__ float sm[];
    float* num  = sm;                 // 1024*17
    float* den  = sm + 1024 * 17;     // 1024
    float* ws1s = den + 1024;         // 32*64
    float* red  = ws1s + 2048;        // 128
    int b = blockIdx.x, t = threadIdx.x;

    for (int i = t; i < 1024 * 17 + 1024; i += 128) sm[i] = 0.0f;
    for (int i = t; i < 2048; i += 128) ws1s[i] = ws1[i];

    float gx = fminf(fmaxf(gaze[b * 2 + 0] * (WW - 1), 0.0f), (float)(WW - 1));
    float gy = fminf(fmaxf(gaze[b * 2 + 1] * (HH - 1), 0.0f), (float)(HH - 1));
    int x0 = (int)floorf(gx), y0 = (int)floorf(gy);

    int k = t;
    float gauss = 0.0f; int xs = 0, ys = 0;
    if (k < KK) {
        int ox = k % KS - (KS / 2);
        int oy = k / KS - (KS / 2);
        xs = min(max(x0 + ox, 0), WW - 1);
        ys = min(max(y0 + oy, 0), HH - 1);
        float dx = (float)xs - gx, dy = (float)ys - gy;
        gauss = expf(-(dx * dx + dy * dy) / (2.0f * SIGMA * SIGMA));
    }
    red[t] = gauss;
    __syncthreads();
    for (int s = 64; s > 0; s >>= 1) {
        if (t < s) red[t] += red[t + s];
        __syncthreads();
    }
    float nsum = fmaxf(red[0], 1e-8f);

    if (k < KK) {
        float nw = gauss / nsum;
        int p = ys * WW + xs;
        float prev[MDIM], wval[MDIM];
        const float* cb = cell + (size_t)b * (MDIM * HW);
        #pragma unroll
        for (int m = 0; m < MDIM; m++) prev[m] = cb[m * HW + p];
        const float* wvb = wv + (size_t)b * (KK * MDIM) + k * MDIM;
        #pragma unroll
        for (int m = 0; m < MDIM; m++) wval[m] = wvb[m];

        float acc = bs2[0];
        for (int j = 0; j < 64; j++) {
            float s = bs1[j];
            #pragma unroll
            for (int i = 0; i < MDIM; i++) s += prev[i] * ws1s[i * 64 + j];
            #pragma unroll
            for (int i = 0; i < MDIM; i++) s += wval[i] * ws1s[(MDIM + i) * 64 + j];
            s = fmaxf(s, 0.0f);
            acc += s * ws2[j];
        }
        float gstr = 1.0f / (1.0f + expf(-acc));
        float w = nw * gstr;
        atomicAdd(&den[p], w);
        #pragma unroll
        for (int m = 0; m < MDIM; m++) {
            float nv = (1.0f - w) * prev[m] + w * wval[m];
            atomicAdd(&num[p * 17 + m], w * nv);
        }
    }
    __syncthreads();

    float* uo = updated_out + (size_t)b * (MDIM * HW);
    __half* uh = updated_h + (size_t)b * (HW * MDIM);
    const float* cb = cell + (size_t)b * (MDIM * HW);
    for (int i = t; i < MDIM * HW; i += 128) {
        int p = i & (HW - 1);
        int m = i >> 10;
        float keep = 1.0f - fminf(den[p], 1.0f);
        float v = keep * cb[i] + num[p * 17 + m];
        uo[i] = v;
        uh[p * MDIM + m] = __float2half(v);    // NHWC fp16 copy for conv1
    }
}

// ---- conv weight prep ----
__global__ void prep_w1_kernel(const float* __restrict__ w, __half* __restrict__ wh) {
    int idx = blockIdx.x * blockDim.x + threadIdx.x;   // (OC=128, IC=16, 3, 3)
    if (idx >= 128 * 16 * 9) return;
    int oc = idx / (16 * 9);
    int rem = idx - oc * (16 * 9);
    int ic = rem / 9;
    int tap = rem - ic * 9;
    wh[(size_t)oc * 144 + tap * 16 + ic] = __float2half(w[idx]);
}
__global__ void prep_w2_kernel(const float* __restrict__ w, __half* __restrict__ wh) {
    int idx = blockIdx.x * blockDim.x + threadIdx.x;   // (OC=64, IC=128, 3, 3)
    if (idx >= 64 * 128 * 9) return;
    int oc = idx / (128 * 9);
    int rem = idx - oc * (128 * 9);
    int ic = rem / 9;
    int tap = rem - ic * 9;
    wh[((size_t)tap * 64 + oc) * 128 + ic] = __float2half(w[idx]);
}

// ================= conv1 (HMMA, halo): 128px x 128oc, K = 9 taps x 16 ============
// One A-halo (6 rows + zero row) + all-taps B staged ONCE; then pure mma.
#define C1_SA   24                     // A row stride (halves)
#define C1_ZR   192                    // zero row index
#define C1_BOFF 9472                   // byte offset of B (A: 193*48=9264)
#define C1_BSTR 152                    // B row stride (halves)
#define C1_SMEM (C1_BOFF + 128*C1_BSTR*2)   // 9472 + 38912 = 48384
__global__ void __launch_bounds__(256) hm_conv1(const __half* __restrict__ uph,
                                                const __half* __restrict__ wh,
                                                const float* __restrict__ bias,
                                                __half* __restrict__ out) {
    extern __shared__ char smraw[];
    __half* As = (__half*)smraw;
    __half* Bs = (__half*)(smraw + C1_BOFF);
    int tid = threadIdx.x, lane = tid & 31, warp = tid >> 5;
    int wm = warp & 3, wn = warp >> 2;       // 4M x 2N; warp tile 32px x 64oc
    int pxt = blockIdx.x, img = blockIdx.z;
    int y0 = pxt * 4;
    const __half* inb = uph + (size_t)img * HW * 16;

    // A halo: 193 rows x 2 chunks of 16B  (row hr = r*32+x, r=0..5 -> sy=y0-1+r; hr 192 = zero row)
    #pragma unroll
    for (int i = 0; i < 2; i++) {
        int idx = tid + i * 256;
        if (idx < 193 * 2) {
            int hr = idx >> 1, c = idx & 1;
            int sy = y0 - 1 + (hr >> 5), sx = hr & 31;
            if (hr < 192 && sy >= 0 && sy < HH)
                cpa16(As + hr * C1_SA + c * 8, inb + (size_t)(sy * WW + sx) * 16 + c * 8);
            else
                *(uint4*)(As + hr * C1_SA + c * 8) = make_uint4(0, 0, 0, 0);
        }
    }
    // B: 128 oc rows x 18 chunks (144 halves)
    #pragma unroll
    for (int i = 0; i < 9; i++) {
        int idx = tid + i * 256;
        int row = idx / 18, c = idx - row * 18;
        cpa16(Bs + row * C1_BSTR + c * 8, wh + (size_t)row * 144 + c * 8);
    }
    CP_COMMIT(); CP_WAIT0();
    __syncthreads();

    float acc[2][8][4] = {};
    #pragma unroll
    for (int tap = 0; tap < 9; tap++) {
        int dy = tap / 3 - 1, dx = tap % 3 - 1;
        uint32_t a[2][4], b[4][4];
        #pragma unroll
        for (int mf = 0; mf < 2; mf++) {
            int p = wm * 32 + mf * 16 + (lane & 15);
            int py = p >> 5, px_ = p & 31;
            int sy = y0 + py + dy, sx = px_ + dx;
            int hr = ((unsigned)sy < (unsigned)HH && (unsigned)sx < (unsigned)WW)
                   ? (py + dy + 1) * 32 + sx : C1_ZR;
            ldsm4(a[mf], As + hr * C1_SA + (lane >> 4) * 8);
        }
        #pragma unroll
        for (int nf2 = 0; nf2 < 4; nf2++) {
            int n = wn * 64 + nf2 * 16 + (lane & 7) + (lane >> 4) * 8;
            int col = tap * 16 + ((lane >> 3) & 1) * 8;
            ldsm4(b[nf2], Bs + n * C1_BSTR + col);
        }
        #pragma unroll
        for (int mf = 0; mf < 2; mf++)
            #pragma unroll
            for (int nf = 0; nf < 8; nf++)
                mma16816(acc[mf][nf], a[mf], b[nf >> 1][(nf & 1) * 2], b[nf >> 1][(nf & 1) * 2 + 1]);
    }

    // epilogue: bias+relu -> fp16 stage in Bs (stride 136) -> coalesced NHWC store
    __syncthreads();
    __half* os = Bs;
    #pragma unroll
    for (int mf = 0; mf < 2; mf++) {
        #pragma unroll
        for (int nf = 0; nf < 8; nf++) {
            int px = wm * 32 + mf * 16 + (lane >> 2);
            int oc = wn * 64 + nf * 8 + 2 * (lane & 3);
            float bb0 = bias[oc], bb1 = bias[oc + 1];
            float v0 = fmaxf(acc[mf][nf][0] + bb0, 0.0f);
            float v1 = fmaxf(acc[mf][nf][1] + bb1, 0.0f);
            *(__half2*)(os + px * 136 + oc) = __floats2half2_rn(v0, v1);
            v0 = fmaxf(acc[mf][nf][2] + bb0, 0.0f);
            v1 = fmaxf(acc[mf][nf][3] + bb1, 0.0f);
            *(__half2*)(os + (px + 8) * 136 + oc) = __floats2half2_rn(v0, v1);
        }
    }
    __syncthreads();
    __half* ob = out + (size_t)img * HW * 128 + (size_t)pxt * 128 * 128;
    #pragma unroll
    for (int i = 0; i < 8; i++) {
        int idx = tid + i * 256;
        int p = idx >> 4, ch = idx & 15;
        *(uint4*)(ob + (size_t)p * 128 + ch * 8) = *(uint4*)(os + p * 136 + ch * 8);
    }
}

// ================= conv2 (HMMA, halo): 128px x 64oc, 9 taps x K=128 ==============
// A-halo staged once; per-tap B double-buffered via cp.async overlapped with mma.
#define C2_SA   136                    // A row stride (halves)
#define C2_ZR   192
#define C2_B0   52608                  // A: 193*272 = 52496, pad
#define C2_B1   (C2_B0 + 17408)       // 64*136*2
#define C2_SMEM (C2_B1 + 17408)       // 87424
__global__ void __launch_bounds__(256) hm_conv2(const __half* __restrict__ y1,
                                                const __half* __restrict__ wh,
                                                const float* __restrict__ bias,
                                                __half* __restrict__ out) {
    extern __shared__ char smraw[];
    __half* As = (__half*)smraw;
    int tid = threadIdx.x, lane = tid & 31, warp = tid >> 5;
    int wm = warp & 3, wn = warp >> 2;       // 4M x 2N; warp tile 32px x 32oc
    int pxt = blockIdx.x, img = blockIdx.z;
    int y0 = pxt * 4;
    const __half* inb = y1 + (size_t)img * HW * 128;

    // A halo: 193 rows x 16 chunks of 16B
    #pragma unroll
    for (int i = 0; i < 13; i++) {
        int idx = tid + i * 256;
        if (idx < 193 * 16) {
            int hr = idx >> 4, c = idx & 15;
            int sy = y0 - 1 + (hr >> 5), sx = hr & 31;
            if (hr < 192 && sy >= 0 && sy < HH)
                cpa16(As + hr * C2_SA + c * 8, inb + (size_t)(sy * WW + sx) * 128 + c * 8);
            else
                *(uint4*)(As + hr * C2_SA + c * 8) = make_uint4(0, 0, 0, 0);
        }
    }
    // B tap 0 into buf0: 64 rows x 16 chunks
    {
        __half* B0 = (__half*)(smraw + C2_B0);
        const __half* wb = wh;
        #pragma unroll
        for (int i = 0; i < 4; i++) {
            int idx = tid + i * 256;
            int row = idx >> 4, c = idx & 15;
            cpa16(B0 + row * C2_SA + c * 8, wb + (size_t)row * 128 + c * 8);
        }
    }
    CP_COMMIT(); CP_WAIT0();
    __syncthreads();

    float acc[2][4][4] = {};
    for (int tap = 0; tap < 9; tap++) {
        __half* Bcur = (__half*)(smraw + ((tap & 1) ? C2_B1 : C2_B0));
        if (tap < 8) {   // prefetch next tap's B into other buffer
            __half* Bnxt = (__half*)(smraw + ((tap & 1) ? C2_B0 : C2_B1));
            const __half* wb = wh + (size_t)(tap + 1) * 64 * 128;
            #pragma unroll
            for (int i = 0; i < 4; i++) {
                int idx = tid + i * 256;
                int row = idx >> 4, c = idx & 15;
                cpa16(Bnxt + row * C2_SA + c * 8, wb + (size_t)row * 128 + c * 8);
            }
            CP_COMMIT();
        }
        int dy = tap / 3 - 1, dx = tap % 3 - 1;
        int hrow[2];
        #pragma unroll
        for (int mf = 0; mf < 2; mf++) {
            int p = wm * 32 + mf * 16 + (lane & 15);
            int py = p >> 5, px_ = p & 31;
            int sy = y0 + py + dy, sx = px_ + dx;
            hrow[mf] = ((unsigned)sy < (unsigned)HH && (unsigned)sx < (unsigned)WW)
                     ? (py + dy + 1) * 32 + sx : C2_ZR;
        }
        #pragma unroll
        for (int ks = 0; ks < 8; ks++) {
            uint32_t a[2][4], b[2][4];
            #pragma unroll
            for (int mf = 0; mf < 2; mf++)
                ldsm4(a[mf], As + hrow[mf] * C2_SA + ks * 16 + (lane >> 4) * 8);
            #pragma unroll
            for (int nf2 = 0; nf2 < 2; nf2++) {
                int n = wn * 32 + nf2 * 16 + (lane & 7) + (lane >> 4) * 8;
                int col = ks * 16 + ((lane >> 3) & 1) * 8;
                ldsm4(b[nf2], Bcur + n * C2_SA + col);
            }
            #pragma unroll
            for (int mf = 0; mf < 2; mf++)
                #pragma unroll
                for (int nf = 0; nf < 4; nf++)
                    mma16816(acc[mf][nf], a[mf], b[nf >> 1][(nf & 1) * 2], b[nf >> 1][(nf & 1) * 2 + 1]);
        }
        if (tap < 8) { CP_WAIT0(); __syncthreads(); }
    }

    // epilogue: bias+relu -> fp16 stage (stride 80, reuse B region) -> NHWC store
    __syncthreads();
    __half* os = (__half*)(smraw + C2_B0);
    #pragma unroll
    for (int mf = 0; mf < 2; mf++) {
        #pragma unroll
        for (int nf = 0; nf < 4; nf++) {
            int px = wm * 32 + mf * 16 + (lane >> 2);
            int oc = wn * 32 + nf * 8 + 2 * (lane & 3);
            float bb0 = bias[oc], bb1 = bias[oc + 1];
            float v0 = fmaxf(acc[mf][nf][0] + bb0, 0.0f);
            float v1 = fmaxf(acc[mf][nf][1] + bb1, 0.0f);
            *(__half2*)(os + px * 80 + oc) = __floats2half2_rn(v0, v1);
            v0 = fmaxf(acc[mf][nf][2] + bb0, 0.0f);
            v1 = fmaxf(acc[mf][nf][3] + bb1, 0.0f);
            *(__half2*)(os + (px + 8) * 80 + oc) = __floats2half2_rn(v0, v1);
        }
    }
    __syncthreads();
    __half* ob = out + (size_t)img * HW * 64 + (size_t)pxt * 128 * 64;
    #pragma unroll
    for (int i = 0; i < 4; i++) {
        int idx = tid + i * 256;
        int p = idx >> 3, ch = idx & 7;
        *(uint4*)(ob + (size_t)p * 64 + ch * 8) = *(uint4*)(os + p * 80 + ch * 8);
    }
}

// ---------------- adaptive avg pool 3x3 from NHWC fp16 --------------------------
__global__ void pool_nhwc_kernel(const __half* __restrict__ y2, float* __restrict__ pooled) {
    int b = blockIdx.x, t = threadIdx.x;     // 576 threads: t = cell*64 + c
    int c = t & 63, cell = t >> 6;
    int i = cell / 3, j = cell % 3;
    int h0 = (i == 0) ? 0 : (i == 1 ? 10 : 21);
    int h1 = (i == 0) ? 11 : (i == 1 ? 22 : 32);
    int w0 = (j == 0) ? 0 : (j == 1 ? 10 : 21);
    int w1 = (j == 0) ? 11 : (j == 1 ? 22 : 32);
    const __half* src = y2 + (size_t)b * HW * 64 + c;
    float s = 0.0f;
    for (int y = h0; y < h1; y++)
        for (int x = w0; x < w1; x++)
            s += __half2float(src[(size_t)(y * WW + x) * 64]);
    pooled[(size_t)b * 576 + c * 9 + cell] = s / (float)((h1 - h0) * (w1 - w0));
}

// ---------------- launch ----------------
extern "C" void kernel_launch(void* const* d_in, const int* in_sizes, int n_in,
                              void* d_out, int out_size) {
    const float* features = (const float*)d_in[0];
    const float* cell     = (const float*)d_in[1];
    const float* gaze     = (const float*)d_in[2];
    const float* w1  = (const float*)d_in[3];
    const float* b1  = (const float*)d_in[4];
    const float* w2  = (const float*)d_in[5];
    const float* b2  = (const float*)d_in[6];
    const float* wvw = (const float*)d_in[7];
    const float* bv  = (const float*)d_in[8];
    const float* ws1 = (const float*)d_in[9];
    const float* bs1 = (const float*)d_in[10];
    const float* ws2 = (const float*)d_in[11];
    const float* bs2 = (const float*)d_in[12];
    const float* ck1 = (const float*)d_in[13];
    const float* cb1 = (const float*)d_in[14];
    const float* ck2 = (const float*)d_in[15];
    const float* cb2 = (const float*)d_in[16];
    const float* wo  = (const float*)d_in[17];
    const float* bo  = (const float*)d_in[18];

    float* out = (float*)d_out;
    float* updated = out + OUT0;

    float *px, *ph1, *ph2, *pwv, *ppool;
    __half *puph, *pwh1, *pwh2, *py1h, *py2h;
    cudaGetSymbolAddress((void**)&px,   g_x);
    cudaGetSymbolAddress((void**)&ph1,  g_h1);
    cudaGetSymbolAddress((void**)&ph2,  g_h2);
    cudaGetSymbolAddress((void**)&pwv,  g_wv);
    cudaGetSymbolAddress((void**)&puph, g_uph);
    cudaGetSymbolAddress((void**)&pwh1, g_wh1);
    cudaGetSymbolAddress((void**)&pwh2, g_wh2);
    cudaGetSymbolAddress((void**)&py1h, g_y1h);
    cudaGetSymbolAddress((void**)&py2h, g_y2h);
    cudaGetSymbolAddress((void**)&ppool,g_pool);

    // 1) x = [features, pe]
    build_x_kernel<<<(BATCH * 576 + 255) / 256, 256>>>(features, gaze, px);

    // 2) MLP chain
    {
        dim3 g(BATCH / 128, 256 / 64);
        gemm_kernel<true><<<g, 256>>>(px, w1, b1, ph1, 576, 256);
    }
    {
        dim3 g(BATCH / 128, 128 / 64);
        gemm_kernel<true><<<g, 256>>>(ph1, w2, b2, ph2, 256, 128);
    }
    {
        dim3 g(BATCH / 128, (1936 + 63) / 64);
        gemm_kernel<false><<<g, 256>>>(ph2, wvw, bv, pwv, 128, 1936);
    }

    // 3) gate + scatter -> updated (fp32 into d_out) + fp16 NHWC copy
    {
        size_t smem = (size_t)(1024 * 17 + 1024 + 2048 + 128) * sizeof(float);
        cudaFuncSetAttribute(gate_scatter_kernel,
                             cudaFuncAttributeMaxDynamicSharedMemorySize, (int)smem);
        gate_scatter_kernel<<<BATCH, 128, smem>>>(cell, gaze, pwv, ws1, bs1, ws2, bs2,
                                                  updated, puph);
    }

    // 4) conv weight prep
    prep_w1_kernel<<<(128 * 16 * 9 + 255) / 256, 256>>>(ck1, pwh1);
    prep_w2_kernel<<<(64 * 128 * 9 + 255) / 256, 256>>>(ck2, pwh2);

    // 5) conv1 (HMMA halo): fp16 NHWC in -> (B,1024,128) fp16 NHWC
    {
        cudaFuncSetAttribute(hm_conv1, cudaFuncAttributeMaxDynamicSharedMemorySize, C1_SMEM);
        dim3 g(8, 1, BATCH);
        hm_conv1<<<g, 256, C1_SMEM>>>(puph, pwh1, cb1, py1h);
    }
    // 6) conv2 (HMMA halo): (B,1024,128) -> (B,1024,64) fp16 NHWC
    {
        cudaFuncSetAttribute(hm_conv2, cudaFuncAttributeMaxDynamicSharedMemorySize, C2_SMEM);
        dim3 g(8, 1, BATCH);
        hm_conv2<<<g, 256, C2_SMEM>>>(py1h, pwh2, cb2, py2h);
    }

    // 7) adaptive pool -> (B,576) fp32
    pool_nhwc_kernel<<<BATCH, 576>>>(py2h, ppool);

    // 8) final linear -> out (B,576)
    {
        dim3 g(BATCH / 128, (576 + 63) / 64);
        gemm_kernel<false><<<g, 256>>>(ppool, wo, bo, out, 576, 576);
    }
}